// round 4
// baseline (speedup 1.0000x reference)
#include <cuda_runtime.h>
#include <math.h>

#define HD 512
#define ND 512
#define BS 8
#define LS 4096
#define NHALF 256
#define NCH 32
#define CHL 128

typedef unsigned long long ull;

// Scratch: Bu (then x) in [b][n][l] float2 layout. 134 MB.
__device__ float2 g_bu[(size_t)BS * ND * LS];
__device__ float2 g_carry[BS * NCH * ND];
__device__ float2 g_cin[BS * NCH * ND];

__device__ __forceinline__ ull fma2(ull a, ull b, ull c) {
    ull d;
    asm("fma.rn.f32x2 %0, %1, %2, %3;" : "=l"(d) : "l"(a), "l"(b), "l"(c));
    return d;
}
__device__ __forceinline__ ull packf2(float lo, float hi) {
    ull d;
    asm("mov.b64 %0, {%1, %2};" : "=l"(d) : "f"(lo), "f"(hi));
    return d;
}
__device__ __forceinline__ float2 unpackf2(ull v) {
    float2 r;
    asm("mov.b64 {%0, %1}, %2;" : "=f"(r.x), "=f"(r.y) : "l"(v));
    return r;
}

__device__ __forceinline__ void lam_of(int n, const float* __restrict__ nu_log,
                                       const float* __restrict__ th_log,
                                       float& lr, float& li) {
    float nu  = expf(nu_log[n]);
    float mag = expf(-nu);
    float th  = expf(th_log[n]);
    float s, c;
    sincosf(th, &s, &c);
    lr = mag * c;
    li = mag * s;
}

// ---------------- GEMM1: Bu[b][n][l] = mask * (u @ Bc), packed f32x2 --------
// acc pair = (real, imag) per complex n. W is naturally (wr, wi) packed.
// A broadcast pairs come from a duplicated shared tile (conflict-free LDS.64).
__global__ __launch_bounds__(256, 2)
void gemm_bu(const float* __restrict__ u, const float* __restrict__ Bw,
             const int* __restrict__ lengths) {
    __shared__ __align__(16) float  As2[16][266];  // duplicated: [k][2*m], m=128
    __shared__ __align__(16) float2 Ws2[16][66];   // permuted complex weights

    int tid = threadIdx.x;
    int tx = tid & 15, ty = tid >> 4;
    int n0 = blockIdx.x * 64;
    int b  = blockIdx.y >> 5;
    int l0 = (blockIdx.y & 31) * 128;

    const float* ub = u + ((size_t)b * LS + l0) * HD;

    ull acc2[8][4] = {};  // (re,im) accumulators: [m 8][n 4]

    for (int k0 = 0; k0 < HD; k0 += 16) {
        // A tile: 128 rows x 16 k, stored duplicated (a,a) for f32x2 broadcast
#pragma unroll
        for (int j = 0; j < 2; j++) {
            int idx = tid + 256 * j;
            int row = idx >> 2, kq = idx & 3;
            float4 f = *(const float4*)(ub + (size_t)row * HD + k0 + kq * 4);
            *(ull*)&As2[kq * 4 + 0][2 * row] = packf2(f.x, f.x);
            *(ull*)&As2[kq * 4 + 1][2 * row] = packf2(f.y, f.y);
            *(ull*)&As2[kq * 4 + 2][2 * row] = packf2(f.z, f.z);
            *(ull*)&As2[kq * 4 + 3][2 * row] = packf2(f.w, f.w);
        }
        // W tile: 16 k x 64 complex n, permuted so lane reads are consecutive:
        // col(n) = (n&3)*16 + (n>>2)  -> lane tx, slot q reads col q*16+tx (n = 4*tx+q)
#pragma unroll
        for (int j = 0; j < 4; j++) {
            int idx = tid + 256 * j;
            int kr = idx >> 6, nc = idx & 63;
            float2 w = *(const float2*)(Bw + 2 * ((size_t)(k0 + kr) * ND + n0 + nc));
            Ws2[kr][(nc & 3) * 16 + (nc >> 2)] = w;
        }
        __syncthreads();

#pragma unroll
        for (int kk = 0; kk < 16; kk++) {
            ull w2[4];
#pragma unroll
            for (int q = 0; q < 4; q++)
                w2[q] = *(const ull*)&Ws2[kk][q * 16 + tx];
#pragma unroll
            for (int i = 0; i < 8; i++) {
                ull a2 = *(const ull*)&As2[kk][2 * (ty * 8 + i)];
#pragma unroll
                for (int q = 0; q < 4; q++)
                    acc2[i][q] = fma2(a2, w2[q], acc2[i][q]);
            }
        }
        __syncthreads();
    }

    int len = lengths[b];
#pragma unroll
    for (int q = 0; q < 4; q++) {
        int n = n0 + 4 * tx + q;
        float2* dst = &g_bu[((size_t)(b * ND + n)) * LS + l0 + ty * 8];
#pragma unroll
        for (int ii = 0; ii < 4; ii++) {
            int l = l0 + ty * 8 + ii * 2;
            float2 v0 = unpackf2(acc2[ii * 2][q]);
            float2 v1 = unpackf2(acc2[ii * 2 + 1][q]);
            float4 v;
            if (l < len)     { v.x = v0.x; v.y = v0.y; } else { v.x = 0.f; v.y = 0.f; }
            if (l + 1 < len) { v.z = v1.x; v.w = v1.y; } else { v.z = 0.f; v.w = 0.f; }
            *(float4*)(dst + ii * 2) = v;
        }
    }
}

// ---------------- Scan phase A: per-chunk local scan (warp per (b,n,chunk)) ---
__global__ __launch_bounds__(256)
void scanA(const float* __restrict__ nu_log, const float* __restrict__ th_log) {
    int gw   = (blockIdx.x * 256 + threadIdx.x) >> 5;
    int lane = threadIdx.x & 31;
    int chunk = gw & (NCH - 1);
    int n     = (gw >> 5) & (ND - 1);
    int b     = gw >> 14;

    float lr, li;
    lam_of(n, nu_log, th_log, lr, li);
    bool rev = (n >= NHALF);

    float2* base = g_bu + ((size_t)(b * ND + n)) * LS;
    int t0 = chunk * CHL + lane * 4;
    int pb = LS - 4 - t0;

    float cr[4], ci[4];
    if (!rev) {
        float4 f0 = *(const float4*)(base + t0);
        float4 f1 = *(const float4*)(base + t0 + 2);
        cr[0] = f0.x; ci[0] = f0.y; cr[1] = f0.z; ci[1] = f0.w;
        cr[2] = f1.x; ci[2] = f1.y; cr[3] = f1.z; ci[3] = f1.w;
    } else {
        float4 f0 = *(const float4*)(base + pb);
        float4 f1 = *(const float4*)(base + pb + 2);
        cr[0] = f1.z; ci[0] = f1.w; cr[1] = f1.x; ci[1] = f1.y;
        cr[2] = f0.z; ci[2] = f0.w; cr[3] = f0.x; ci[3] = f0.y;
    }

    float yr[4], yi[4];
    yr[0] = cr[0]; yi[0] = ci[0];
#pragma unroll
    for (int i = 1; i < 4; i++) {
        yr[i] = fmaf(lr, yr[i - 1], fmaf(-li, yi[i - 1], cr[i]));
        yi[i] = fmaf(lr, yi[i - 1], fmaf( li, yr[i - 1], ci[i]));
    }

    float l2r = lr * lr - li * li, l2i = 2.f * lr * li;
    float fr  = l2r * l2r - l2i * l2i, fi = 2.f * l2r * l2i;

    float sr = yr[3], si = yi[3];
#pragma unroll
    for (int s = 1; s < 32; s <<= 1) {
        float pr_ = __shfl_up_sync(0xffffffffu, sr, s);
        float pi_ = __shfl_up_sync(0xffffffffu, si, s);
        if (lane >= s) {
            sr = fmaf(fr, pr_, fmaf(-fi, pi_, sr));
            si = fmaf(fr, pi_, fmaf( fi, pr_, si));
        }
        float nfr = fr * fr - fi * fi;
        fi = 2.f * fr * fi;
        fr = nfr;
    }
    float car = __shfl_up_sync(0xffffffffu, sr, 1);
    float cai = __shfl_up_sync(0xffffffffu, si, 1);
    if (lane == 0) { car = 0.f; cai = 0.f; }

    float pr = lr, pi = li;
    float xr[4], xi[4];
#pragma unroll
    for (int i = 0; i < 4; i++) {
        xr[i] = yr[i] + pr * car - pi * cai;
        xi[i] = yi[i] + pr * cai + pi * car;
        float t = pr * lr - pi * li;
        pi = pr * li + pi * lr;
        pr = t;
    }

    if (lane == 31) g_carry[(b * NCH + chunk) * ND + n] = make_float2(sr, si);

    if (!rev) {
        *(float4*)(base + t0)     = make_float4(xr[0], xi[0], xr[1], xi[1]);
        *(float4*)(base + t0 + 2) = make_float4(xr[2], xi[2], xr[3], xi[3]);
    } else {
        *(float4*)(base + pb)     = make_float4(xr[3], xi[3], xr[2], xi[2]);
        *(float4*)(base + pb + 2) = make_float4(xr[1], xi[1], xr[0], xi[0]);
    }
}

// ---------------- Scan phase B: inter-chunk carry scan -----------------------
__global__ void scanB(const float* __restrict__ nu_log, const float* __restrict__ th_log) {
    int t = blockIdx.x * blockDim.x + threadIdx.x;
    int n = t & (ND - 1);
    int b = t >> 9;

    float lr, li;
    lam_of(n, nu_log, th_log, lr, li);
    float ar = lr, ai = li;
#pragma unroll
    for (int s = 0; s < 7; s++) {
        float t2 = ar * ar - ai * ai;
        ai = 2.f * ar * ai;
        ar = t2;
    }

    float pr = 0.f, pi = 0.f;
    for (int c = 0; c < NCH; c++) {
        int idx = (b * NCH + c) * ND + n;
        g_cin[idx] = make_float2(pr, pi);
        float2 s2 = g_carry[idx];
        float t2 = fmaf(ar, pr, fmaf(-ai, pi, s2.x));
        pi = fmaf(ar, pi, fmaf(ai, pr, s2.y));
        pr = t2;
    }
}

// ---------------- Scan phase C: apply chunk carries + length masking ---------
__global__ __launch_bounds__(256)
void scanC(const int* __restrict__ lengths, const float* __restrict__ nu_log,
           const float* __restrict__ th_log) {
    int gw   = (blockIdx.x * 256 + threadIdx.x) >> 5;
    int lane = threadIdx.x & 31;
    int chunk = gw & (NCH - 1);
    int n     = (gw >> 5) & (ND - 1);
    int b     = gw >> 14;

    float lr, li;
    lam_of(n, nu_log, th_log, lr, li);
    bool rev = (n >= NHALF);
    int len = lengths[b];

    float2* base = g_bu + ((size_t)(b * ND + n)) * LS;
    int t0 = chunk * CHL + lane * 4;
    int pb = LS - 4 - t0;

    float xr[4], xi[4];
    if (!rev) {
        float4 f0 = *(const float4*)(base + t0);
        float4 f1 = *(const float4*)(base + t0 + 2);
        xr[0] = f0.x; xi[0] = f0.y; xr[1] = f0.z; xi[1] = f0.w;
        xr[2] = f1.x; xi[2] = f1.y; xr[3] = f1.z; xi[3] = f1.w;
    } else {
        float4 f0 = *(const float4*)(base + pb);
        float4 f1 = *(const float4*)(base + pb + 2);
        xr[0] = f1.z; xi[0] = f1.w; xr[1] = f1.x; xi[1] = f1.y;
        xr[2] = f0.z; xi[2] = f0.w; xr[3] = f0.x; xi[3] = f0.y;
    }

    float2 C = g_cin[(b * NCH + chunk) * ND + n];

    float l2r = lr * lr - li * li, l2i = 2.f * lr * li;
    float f4r = l2r * l2r - l2i * l2i, f4i = 2.f * l2r * l2i;
    float p4r = 1.f, p4i = 0.f, qr = f4r, qi = f4i;
#pragma unroll
    for (int bit = 0; bit < 5; bit++) {
        if (lane & (1 << bit)) {
            float t2 = p4r * qr - p4i * qi;
            p4i = p4r * qi + p4i * qr;
            p4r = t2;
        }
        float t3 = qr * qr - qi * qi;
        qi = 2.f * qr * qi;
        qr = t3;
    }
    float pwr = p4r * lr - p4i * li;
    float pwi = p4r * li + p4i * lr;

#pragma unroll
    for (int i = 0; i < 4; i++) {
        xr[i] += pwr * C.x - pwi * C.y;
        xi[i] += pwr * C.y + pwi * C.x;
        float t2 = pwr * lr - pwi * li;
        pwi = pwr * li + pwi * lr;
        pwr = t2;
        int l = rev ? (LS - 1 - (t0 + i)) : (t0 + i);
        if (l >= len) { xr[i] = 0.f; xi[i] = 0.f; }
    }

    if (!rev) {
        *(float4*)(base + t0)     = make_float4(xr[0], xi[0], xr[1], xi[1]);
        *(float4*)(base + t0 + 2) = make_float4(xr[2], xi[2], xr[3], xi[3]);
    } else {
        *(float4*)(base + pb)     = make_float4(xr[3], xi[3], xr[2], xi[2]);
        *(float4*)(base + pb + 2) = make_float4(xr[1], xi[1], xr[0], xi[0]);
    }
}

// ---------------- GEMM2: y = xr@C0 - xi@C1, packed f32x2 ---------------------
// acc packs adjacent j-pairs; C pairs are contiguous -> permuted conflict-free
// LDS.64. x re/im broadcasts via duplicated shared tiles (imag pre-negated).
__global__ __launch_bounds__(256, 2)
void gemm_y(const float* __restrict__ Cw, float* __restrict__ out) {
    __shared__ __align__(16) float  XsR2[8][260];   // duplicated real
    __shared__ __align__(16) float  XsI2n[8][260];  // duplicated -imag
    __shared__ __align__(16) float2 W0s[8][66];     // permuted C0 pairs
    __shared__ __align__(16) float2 W1s[8][66];     // permuted -C1 pairs... (negation folded in XsI2n instead)

    int tid = threadIdx.x;
    int tx = tid & 15, ty = tid >> 4;
    int j0 = blockIdx.x * 128;
    int b  = blockIdx.y >> 5;
    int l0 = (blockIdx.y & 31) * 128;

    const float* C0 = Cw;
    const float* C1 = Cw + (size_t)HD * ND;

    ull acc2[8][4] = {};  // [l 8][j-pair 4]

    for (int k0 = 0; k0 < ND; k0 += 8) {
        // X tile: 8 k x 128 l complex -> duplicated re and -im
#pragma unroll
        for (int jj = 0; jj < 2; jj++) {
            int idx = tid + 256 * jj;
            int kr = idx >> 6, lc = (idx & 63) * 2;
            float4 f = *(const float4*)(g_bu + ((size_t)(b * ND + k0 + kr)) * LS + l0 + lc);
            *(ull*)&XsR2[kr][2 * lc]      = packf2(f.x, f.x);
            *(ull*)&XsR2[kr][2 * lc + 2]  = packf2(f.z, f.z);
            *(ull*)&XsI2n[kr][2 * lc]     = packf2(-f.y, -f.y);
            *(ull*)&XsI2n[kr][2 * lc + 2] = packf2(-f.w, -f.w);
        }
        // W tiles: pair p (j=2p,2p+1) stored at col(p) = (p&3)*16 + (p>>2)
        {
            int kr = tid >> 5, jc = (tid & 31) * 4;
            int p0 = jc >> 1;
            float4 w0 = *(const float4*)(C0 + (size_t)(k0 + kr) * ND + j0 + jc);
            float4 w1 = *(const float4*)(C1 + (size_t)(k0 + kr) * ND + j0 + jc);
            int c0 = (p0 & 3) * 16 + (p0 >> 2);
            int c1 = ((p0 + 1) & 3) * 16 + ((p0 + 1) >> 2);
            *(ull*)&W0s[kr][c0] = packf2(w0.x, w0.y);
            *(ull*)&W0s[kr][c1] = packf2(w0.z, w0.w);
            *(ull*)&W1s[kr][c0] = packf2(w1.x, w1.y);
            *(ull*)&W1s[kr][c1] = packf2(w1.z, w1.w);
        }
        __syncthreads();

#pragma unroll
        for (int kk = 0; kk < 8; kk++) {
            ull w0p[4], w1p[4];
#pragma unroll
            for (int q = 0; q < 4; q++) {
                w0p[q] = *(const ull*)&W0s[kk][q * 16 + tx];
                w1p[q] = *(const ull*)&W1s[kk][q * 16 + tx];
            }
#pragma unroll
            for (int i = 0; i < 8; i++) {
                ull ar2 = *(const ull*)&XsR2[kk][2 * (ty * 8 + i)];
                ull ai2 = *(const ull*)&XsI2n[kk][2 * (ty * 8 + i)];
#pragma unroll
                for (int q = 0; q < 4; q++) {
                    acc2[i][q] = fma2(ar2, w0p[q], acc2[i][q]);
                    acc2[i][q] = fma2(ai2, w1p[q], acc2[i][q]);
                }
            }
        }
        __syncthreads();
    }

    // pair p = 4*tx+q -> j = 8*tx + 2*q
    float* ob = out + ((size_t)b * LS + l0) * HD + j0;
#pragma unroll
    for (int i = 0; i < 8; i++) {
        size_t row = (size_t)(ty * 8 + i) * HD;
#pragma unroll
        for (int q = 0; q < 4; q++) {
            float2 v = unpackf2(acc2[i][q]);
            *(float2*)&ob[row + 8 * tx + 2 * q] = v;
        }
    }
}

extern "C" void kernel_launch(void* const* d_in, const int* in_sizes, int n_in,
                              void* d_out, int out_size) {
    const float* u         = (const float*)d_in[0];
    const int*   lengths   = (const int*)d_in[1];
    const float* nu_log    = (const float*)d_in[2];
    const float* theta_log = (const float*)d_in[3];
    const float* Bw        = (const float*)d_in[4];
    const float* Cw        = (const float*)d_in[5];
    float* out = (float*)d_out;

    dim3 g1(ND / 64, (BS * LS) / 128);   // (8, 256)
    gemm_bu<<<g1, 256>>>(u, Bw, lengths);

    scanA<<<16384, 256>>>(nu_log, theta_log);
    scanB<<<16, 256>>>(nu_log, theta_log);
    scanC<<<16384, 256>>>(lengths, nu_log, theta_log);

    dim3 g2(HD / 128, (BS * LS) / 128);  // (4, 256)
    gemm_y<<<g2, 256>>>(Cw, out);
}

// round 6
// speedup vs baseline: 3.6547x; 3.6547x over previous
#include <cuda_runtime.h>
#include <math.h>
#include <stdint.h>

#define HD 512
#define ND 512
#define BS 8
#define LS 4096
#define NHALF 256
#define NCH 32
#define CHL 128

// Scratch: Bu (then x) in [b][n][l] float2 layout (134 MB) + transposed tf32 B'.
__device__ float2 g_bu[(size_t)BS * ND * LS];
__device__ float2 g_carry[BS * NCH * ND];
__device__ float2 g_cin[BS * NCH * ND];
__device__ float  g_bt[(size_t)1024 * 512];   // B'[n'=2n+c][h], tf32-rounded

// ---------------------------------------------------------------- helpers ---
__device__ __forceinline__ float tf32r(float f) {
    uint32_t t;
    asm("cvt.rna.tf32.f32 %0, %1;" : "=r"(t) : "f"(f));
    return __uint_as_float(t);
}
__device__ __forceinline__ void mma8(float* d, const uint32_t* a, uint32_t b0, uint32_t b1) {
    asm volatile(
        "mma.sync.aligned.m16n8k8.row.col.f32.tf32.tf32.f32 "
        "{%0,%1,%2,%3}, {%4,%5,%6,%7}, {%8,%9}, {%0,%1,%2,%3};"
        : "+f"(d[0]), "+f"(d[1]), "+f"(d[2]), "+f"(d[3])
        : "r"(a[0]), "r"(a[1]), "r"(a[2]), "r"(a[3]), "r"(b0), "r"(b1));
}
__device__ __forceinline__ void lam_of(int n, const float* __restrict__ nu_log,
                                       const float* __restrict__ th_log,
                                       float& lr, float& li) {
    float nu  = expf(nu_log[n]);
    float mag = expf(-nu);
    float th  = expf(th_log[n]);
    float s, c;
    sincosf(th, &s, &c);
    lr = mag * c;
    li = mag * s;
}

// ------------------------------------------------- prep: B' = B^T (tf32) ----
__global__ __launch_bounds__(256)
void bt_prep(const float* __restrict__ Bw) {
    int idx = blockIdx.x * 256 + threadIdx.x;   // 0 .. 1024*512-1
    int h  = idx & 511;
    int np = idx >> 9;
    g_bt[(size_t)np * 512 + h] = tf32r(Bw[(size_t)h * 1024 + np]);
}

// -------- GEMM1 (mma.sync tf32): D[l][n'] = u @ B'^T, (re,im) pairs --------
// CTA 128(l) x 128(n'), 8 warps 4x2, warp 32x64 (2x8 frags of 16x8).
__global__ __launch_bounds__(256)
void gemm_bu_mma(const float* __restrict__ u, const int* __restrict__ lengths) {
    __shared__ float As[128][36];   // [l][k]
    __shared__ float Bs[128][36];   // [n'][k]

    int tid = threadIdx.x;
    int wid = tid >> 5, lane = tid & 31;
    int g = lane >> 2, t = lane & 3;
    int wm = wid >> 1, wn = wid & 1;

    int np0 = blockIdx.x * 128;
    int b   = blockIdx.y >> 5;
    int l0  = (blockIdx.y & 31) * 128;

    const float* ua = u + ((size_t)b * LS + l0) * HD;

    float acc[2][8][4];
#pragma unroll
    for (int mi = 0; mi < 2; mi++)
#pragma unroll
        for (int ni = 0; ni < 8; ni++)
#pragma unroll
            for (int q = 0; q < 4; q++) acc[mi][ni][q] = 0.f;

    for (int c = 0; c < 16; ++c) {
        int k0 = c * 32;
        // A tile: 128 x 32 (cvt tf32). 1024 float4 / 256 thr = 4 each.
#pragma unroll
        for (int i = 0; i < 4; i++) {
            int idx = tid + 256 * i;
            int row = idx >> 3, c4 = idx & 7;
            float4 f = *(const float4*)(ua + (size_t)row * HD + k0 + c4 * 4);
            float4 o = make_float4(tf32r(f.x), tf32r(f.y), tf32r(f.z), tf32r(f.w));
            *(float4*)&As[row][c4 * 4] = o;
        }
        // B tile: 128 x 32, already tf32 in g_bt.
#pragma unroll
        for (int i = 0; i < 4; i++) {
            int idx = tid + 256 * i;
            int row = idx >> 3, c4 = idx & 7;
            *(float4*)&Bs[row][c4 * 4] =
                *(const float4*)(g_bt + (size_t)(np0 + row) * 512 + k0 + c4 * 4);
        }
        __syncthreads();

#pragma unroll
        for (int ks = 0; ks < 4; ks++) {
            int kb = ks * 8;
            uint32_t a[2][4];
#pragma unroll
            for (int mi = 0; mi < 2; mi++) {
                int rb = wm * 32 + mi * 16;
                a[mi][0] = __float_as_uint(As[rb + g][kb + t]);
                a[mi][1] = __float_as_uint(As[rb + g + 8][kb + t]);
                a[mi][2] = __float_as_uint(As[rb + g][kb + t + 4]);
                a[mi][3] = __float_as_uint(As[rb + g + 8][kb + t + 4]);
            }
#pragma unroll
            for (int ni = 0; ni < 8; ni++) {
                int nb = wn * 64 + ni * 8;
                uint32_t b0 = __float_as_uint(Bs[nb + g][kb + t]);
                uint32_t b1 = __float_as_uint(Bs[nb + g][kb + t + 4]);
#pragma unroll
                for (int mi = 0; mi < 2; mi++)
                    mma8(acc[mi][ni], a[mi], b0, b1);
            }
        }
        __syncthreads();
    }

    // Epilogue: (c0,c1) = (re,im) for complex n; write masked float2.
    int len = lengths[b];
#pragma unroll
    for (int mi = 0; mi < 2; mi++) {
        int l_lo = l0 + wm * 32 + mi * 16 + g;
        int l_hi = l_lo + 8;
        bool v0 = l_lo < len, v1 = l_hi < len;
#pragma unroll
        for (int ni = 0; ni < 8; ni++) {
            int n = (np0 >> 1) + wn * 32 + ni * 4 + t;
            float2* row = &g_bu[((size_t)(b * ND + n)) * LS];
            row[l_lo] = v0 ? make_float2(acc[mi][ni][0], acc[mi][ni][1])
                           : make_float2(0.f, 0.f);
            row[l_hi] = v1 ? make_float2(acc[mi][ni][2], acc[mi][ni][3])
                           : make_float2(0.f, 0.f);
        }
    }
}

// ---------------- Scan phase A: per-chunk local scan (warp per (b,n,chunk)) ---
__global__ __launch_bounds__(256)
void scanA(const float* __restrict__ nu_log, const float* __restrict__ th_log) {
    int gw   = (blockIdx.x * 256 + threadIdx.x) >> 5;
    int lane = threadIdx.x & 31;
    int chunk = gw & (NCH - 1);
    int n     = (gw >> 5) & (ND - 1);
    int b     = gw >> 14;

    float lr, li;
    lam_of(n, nu_log, th_log, lr, li);
    bool rev = (n >= NHALF);

    float2* base = g_bu + ((size_t)(b * ND + n)) * LS;
    int t0 = chunk * CHL + lane * 4;
    int pb = LS - 4 - t0;

    float cr[4], ci[4];
    if (!rev) {
        float4 f0 = *(const float4*)(base + t0);
        float4 f1 = *(const float4*)(base + t0 + 2);
        cr[0] = f0.x; ci[0] = f0.y; cr[1] = f0.z; ci[1] = f0.w;
        cr[2] = f1.x; ci[2] = f1.y; cr[3] = f1.z; ci[3] = f1.w;
    } else {
        float4 f0 = *(const float4*)(base + pb);
        float4 f1 = *(const float4*)(base + pb + 2);
        cr[0] = f1.z; ci[0] = f1.w; cr[1] = f1.x; ci[1] = f1.y;
        cr[2] = f0.z; ci[2] = f0.w; cr[3] = f0.x; ci[3] = f0.y;
    }

    float yr[4], yi[4];
    yr[0] = cr[0]; yi[0] = ci[0];
#pragma unroll
    for (int i = 1; i < 4; i++) {
        yr[i] = fmaf(lr, yr[i - 1], fmaf(-li, yi[i - 1], cr[i]));
        yi[i] = fmaf(lr, yi[i - 1], fmaf( li, yr[i - 1], ci[i]));
    }

    float l2r = lr * lr - li * li, l2i = 2.f * lr * li;
    float fr  = l2r * l2r - l2i * l2i, fi = 2.f * l2r * l2i;

    float sr = yr[3], si = yi[3];
#pragma unroll
    for (int s = 1; s < 32; s <<= 1) {
        float pr_ = __shfl_up_sync(0xffffffffu, sr, s);
        float pi_ = __shfl_up_sync(0xffffffffu, si, s);
        if (lane >= s) {
            sr = fmaf(fr, pr_, fmaf(-fi, pi_, sr));
            si = fmaf(fr, pi_, fmaf( fi, pr_, si));
        }
        float nfr = fr * fr - fi * fi;
        fi = 2.f * fr * fi;
        fr = nfr;
    }
    float car = __shfl_up_sync(0xffffffffu, sr, 1);
    float cai = __shfl_up_sync(0xffffffffu, si, 1);
    if (lane == 0) { car = 0.f; cai = 0.f; }

    float pr = lr, pi = li;
    float xr[4], xi[4];
#pragma unroll
    for (int i = 0; i < 4; i++) {
        xr[i] = yr[i] + pr * car - pi * cai;
        xi[i] = yi[i] + pr * cai + pi * car;
        float t = pr * lr - pi * li;
        pi = pr * li + pi * lr;
        pr = t;
    }

    if (lane == 31) g_carry[(b * NCH + chunk) * ND + n] = make_float2(sr, si);

    if (!rev) {
        *(float4*)(base + t0)     = make_float4(xr[0], xi[0], xr[1], xi[1]);
        *(float4*)(base + t0 + 2) = make_float4(xr[2], xi[2], xr[3], xi[3]);
    } else {
        *(float4*)(base + pb)     = make_float4(xr[3], xi[3], xr[2], xi[2]);
        *(float4*)(base + pb + 2) = make_float4(xr[1], xi[1], xr[0], xi[0]);
    }
}

// ---------------- Scan phase B: inter-chunk carry scan -----------------------
__global__ void scanB(const float* __restrict__ nu_log, const float* __restrict__ th_log) {
    int t = blockIdx.x * blockDim.x + threadIdx.x;
    int n = t & (ND - 1);
    int b = t >> 9;

    float lr, li;
    lam_of(n, nu_log, th_log, lr, li);
    float ar = lr, ai = li;
#pragma unroll
    for (int s = 0; s < 7; s++) {
        float t2 = ar * ar - ai * ai;
        ai = 2.f * ar * ai;
        ar = t2;
    }

    float pr = 0.f, pi = 0.f;
    for (int c = 0; c < NCH; c++) {
        int idx = (b * NCH + c) * ND + n;
        g_cin[idx] = make_float2(pr, pi);
        float2 s2 = g_carry[idx];
        float t2 = fmaf(ar, pr, fmaf(-ai, pi, s2.x));
        pi = fmaf(ar, pi, fmaf(ai, pr, s2.y));
        pr = t2;
    }
}

// ---------------- Scan phase C: apply chunk carries + length masking ---------
__global__ __launch_bounds__(256)
void scanC(const int* __restrict__ lengths, const float* __restrict__ nu_log,
           const float* __restrict__ th_log) {
    int gw   = (blockIdx.x * 256 + threadIdx.x) >> 5;
    int lane = threadIdx.x & 31;
    int chunk = gw & (NCH - 1);
    int n     = (gw >> 5) & (ND - 1);
    int b     = gw >> 14;

    float lr, li;
    lam_of(n, nu_log, th_log, lr, li);
    bool rev = (n >= NHALF);
    int len = lengths[b];

    float2* base = g_bu + ((size_t)(b * ND + n)) * LS;
    int t0 = chunk * CHL + lane * 4;
    int pb = LS - 4 - t0;

    float xr[4], xi[4];
    if (!rev) {
        float4 f0 = *(const float4*)(base + t0);
        float4 f1 = *(const float4*)(base + t0 + 2);
        xr[0] = f0.x; xi[0] = f0.y; xr[1] = f0.z; xi[1] = f0.w;
        xr[2] = f1.x; xi[2] = f1.y; xr[3] = f1.z; xi[3] = f1.w;
    } else {
        float4 f0 = *(const float4*)(base + pb);
        float4 f1 = *(const float4*)(base + pb + 2);
        xr[0] = f1.z; xi[0] = f1.w; xr[1] = f1.x; xi[1] = f1.y;
        xr[2] = f0.z; xi[2] = f0.w; xr[3] = f0.x; xi[3] = f0.y;
    }

    float2 C = g_cin[(b * NCH + chunk) * ND + n];

    float l2r = lr * lr - li * li, l2i = 2.f * lr * li;
    float f4r = l2r * l2r - l2i * l2i, f4i = 2.f * l2r * l2i;
    float p4r = 1.f, p4i = 0.f, qr = f4r, qi = f4i;
#pragma unroll
    for (int bit = 0; bit < 5; bit++) {
        if (lane & (1 << bit)) {
            float t2 = p4r * qr - p4i * qi;
            p4i = p4r * qi + p4i * qr;
            p4r = t2;
        }
        float t3 = qr * qr - qi * qi;
        qi = 2.f * qr * qi;
        qr = t3;
    }
    float pwr = p4r * lr - p4i * li;
    float pwi = p4r * li + p4i * lr;

#pragma unroll
    for (int i = 0; i < 4; i++) {
        xr[i] += pwr * C.x - pwi * C.y;
        xi[i] += pwr * C.y + pwi * C.x;
        float t2 = pwr * lr - pwi * li;
        pwi = pwr * li + pwi * lr;
        pwr = t2;
        int l = rev ? (LS - 1 - (t0 + i)) : (t0 + i);
        if (l >= len) { xr[i] = 0.f; xi[i] = 0.f; }
    }

    if (!rev) {
        *(float4*)(base + t0)     = make_float4(xr[0], xi[0], xr[1], xi[1]);
        *(float4*)(base + t0 + 2) = make_float4(xr[2], xi[2], xr[3], xi[3]);
    } else {
        *(float4*)(base + pb)     = make_float4(xr[3], xi[3], xr[2], xi[2]);
        *(float4*)(base + pb + 2) = make_float4(xr[1], xi[1], xr[0], xi[0]);
    }
}

// -------- GEMM2 (mma.sync tf32): y = x2 @ Cc, Cc rows (C0[n], -C1[n]) -------
__global__ __launch_bounds__(256)
void gemm_y_mma(const float* __restrict__ Cw, float* __restrict__ out) {
    __shared__ float As[128][36];    // [l][k' local 32]
    __shared__ float Bs[32][132];    // [k' local][j 128]

    int tid = threadIdx.x;
    int wid = tid >> 5, lane = tid & 31;
    int g = lane >> 2, t = lane & 3;
    int wm = wid >> 1, wn = wid & 1;

    int j0 = blockIdx.x * 128;
    int b  = blockIdx.y >> 5;
    int l0 = (blockIdx.y & 31) * 128;

    float acc[2][8][4];
#pragma unroll
    for (int mi = 0; mi < 2; mi++)
#pragma unroll
        for (int ni = 0; ni < 8; ni++)
#pragma unroll
            for (int q = 0; q < 4; q++) acc[mi][ni][q] = 0.f;

    for (int c = 0; c < 32; ++c) {
        int k0 = c * 32;           // k' base (even); complex n base = k0/2
        // A tile: 16 n x 128 l float2 -> As[l][2n..2n+1] (cvt tf32)
#pragma unroll
        for (int i = 0; i < 8; i++) {
            int idx = tid + 256 * i;
            int ni = idx >> 7, li = idx & 127;
            float2 v = g_bu[((size_t)(b * ND + (k0 >> 1) + ni)) * LS + l0 + li];
            *(float2*)&As[li][2 * ni] = make_float2(tf32r(v.x), tf32r(v.y));
        }
        // B tile: 32 k' x 128 j; odd k' rows are -C1.
#pragma unroll
        for (int i = 0; i < 4; i++) {
            int idx = tid + 256 * i;
            int row = idx >> 5, c4 = idx & 31;
            int cc = row & 1;
            int n  = (k0 + row) >> 1;
            float4 f = *(const float4*)(Cw + (size_t)cc * HD * ND + (size_t)n * ND + j0 + c4 * 4);
            float s = cc ? -1.f : 1.f;
            *(float4*)&Bs[row][c4 * 4] =
                make_float4(tf32r(s * f.x), tf32r(s * f.y), tf32r(s * f.z), tf32r(s * f.w));
        }
        __syncthreads();

#pragma unroll
        for (int ks = 0; ks < 4; ks++) {
            int kb = ks * 8;
            uint32_t a[2][4];
#pragma unroll
            for (int mi = 0; mi < 2; mi++) {
                int rb = wm * 32 + mi * 16;
                a[mi][0] = __float_as_uint(As[rb + g][kb + t]);
                a[mi][1] = __float_as_uint(As[rb + g + 8][kb + t]);
                a[mi][2] = __float_as_uint(As[rb + g][kb + t + 4]);
                a[mi][3] = __float_as_uint(As[rb + g + 8][kb + t + 4]);
            }
#pragma unroll
            for (int ni = 0; ni < 8; ni++) {
                int jb = wn * 64 + ni * 8;
                uint32_t b0 = __float_as_uint(Bs[kb + t][jb + g]);
                uint32_t b1 = __float_as_uint(Bs[kb + t + 4][jb + g]);
#pragma unroll
                for (int mi = 0; mi < 2; mi++)
                    mma8(acc[mi][ni], a[mi], b0, b1);
            }
        }
        __syncthreads();
    }

    // Epilogue: (c0,c1) = adjacent j pair.
#pragma unroll
    for (int mi = 0; mi < 2; mi++) {
        int l_lo = l0 + wm * 32 + mi * 16 + g;
        int l_hi = l_lo + 8;
#pragma unroll
        for (int ni = 0; ni < 8; ni++) {
            int j = j0 + wn * 64 + ni * 8 + 2 * t;
            *(float2*)&out[((size_t)b * LS + l_lo) * HD + j] =
                make_float2(acc[mi][ni][0], acc[mi][ni][1]);
            *(float2*)&out[((size_t)b * LS + l_hi) * HD + j] =
                make_float2(acc[mi][ni][2], acc[mi][ni][3]);
        }
    }
}

extern "C" void kernel_launch(void* const* d_in, const int* in_sizes, int n_in,
                              void* d_out, int out_size) {
    const float* u         = (const float*)d_in[0];
    const int*   lengths   = (const int*)d_in[1];
    const float* nu_log    = (const float*)d_in[2];
    const float* theta_log = (const float*)d_in[3];
    const float* Bw        = (const float*)d_in[4];
    const float* Cw        = (const float*)d_in[5];
    float* out = (float*)d_out;

    bt_prep<<<2048, 256>>>(Bw);

    dim3 g1(1024 / 128, (BS * LS) / 128);   // (8, 256)
    gemm_bu_mma<<<g1, 256>>>(u, lengths);

    scanA<<<16384, 256>>>(nu_log, theta_log);
    scanB<<<16, 256>>>(nu_log, theta_log);
    scanC<<<16384, 256>>>(lengths, nu_log, theta_log);

    dim3 g2(HD / 128, (BS * LS) / 128);     // (4, 256)
    gemm_y_mma<<<g2, 256>>>(Cw, out);
}

// round 8
// speedup vs baseline: 4.8925x; 1.3387x over previous
#include <cuda_runtime.h>
#include <math.h>
#include <stdint.h>

#define HD 512
#define ND 512
#define BS 8
#define LS 4096
#define NHALF 256
#define NCH 32
#define CHL 128
#define PAD 36
#define ABYTES (128 * PAD * 4)

// Scratch buffers.
__device__ float2 g_bu[(size_t)BS * ND * LS];      // Bu / x, [b][n][l]
__device__ float2 g_carry[BS * NCH * ND];
__device__ float2 g_cin[BS * NCH * ND];
__device__ float  g_ut[(size_t)BS * LS * HD];      // tf32-rounded u
__device__ float  g_bt[(size_t)1024 * 512];        // B'[n'=2n+c][h], tf32
__device__ float  g_ct[(size_t)512 * 1024];        // Cc[j][k'=2n+c] = (C0,-C1), tf32

// ---------------------------------------------------------------- helpers ---
__device__ __forceinline__ float tf32r(float f) {
    uint32_t t;
    asm("cvt.rna.tf32.f32 %0, %1;" : "=r"(t) : "f"(f));
    return __uint_as_float(t);
}
__device__ __forceinline__ void mma8(float* d, const uint32_t* a, uint32_t b0, uint32_t b1) {
    asm volatile(
        "mma.sync.aligned.m16n8k8.row.col.f32.tf32.tf32.f32 "
        "{%0,%1,%2,%3}, {%4,%5,%6,%7}, {%8,%9}, {%0,%1,%2,%3};"
        : "+f"(d[0]), "+f"(d[1]), "+f"(d[2]), "+f"(d[3])
        : "r"(a[0]), "r"(a[1]), "r"(a[2]), "r"(a[3]), "r"(b0), "r"(b1));
}
__device__ __forceinline__ void ldsm4(uint32_t* r, uint32_t addr) {
    asm volatile("ldmatrix.sync.aligned.m8n8.x4.shared.b16 {%0,%1,%2,%3}, [%4];"
                 : "=r"(r[0]), "=r"(r[1]), "=r"(r[2]), "=r"(r[3]) : "r"(addr));
}
__device__ __forceinline__ void cpa16(uint32_t dst, const float* src) {
    asm volatile("cp.async.cg.shared.global [%0], [%1], 16;" :: "r"(dst), "l"(src));
}
#define CP_COMMIT() asm volatile("cp.async.commit_group;")
#define CP_WAIT(N)  asm volatile("cp.async.wait_group %0;" :: "n"(N))

__device__ __forceinline__ void lam_of(int n, const float* __restrict__ nu_log,
                                       const float* __restrict__ th_log,
                                       float& lr, float& li) {
    float nu  = expf(nu_log[n]);
    float mag = expf(-nu);
    float th  = expf(th_log[n]);
    float s, c;
    sincosf(th, &s, &c);
    lr = mag * c;
    li = mag * s;
}

// ---------------------------------------------------------------- preps -----
__global__ __launch_bounds__(256)
void prep_u(const float* __restrict__ u) {
    size_t idx = (size_t)blockIdx.x * 256 + threadIdx.x;   // float4 index
#pragma unroll
    for (int i = 0; i < 4; i++) {
        size_t j = idx + (size_t)i * 1048576;
        float4 f = *(const float4*)(u + j * 4);
        float4 o = make_float4(tf32r(f.x), tf32r(f.y), tf32r(f.z), tf32r(f.w));
        *(float4*)(g_ut + j * 4) = o;
    }
}
__global__ __launch_bounds__(256)
void bt_prep(const float* __restrict__ Bw) {
    int idx = blockIdx.x * 256 + threadIdx.x;
    int h  = idx & 511;
    int np = idx >> 9;
    g_bt[(size_t)np * 512 + h] = tf32r(Bw[(size_t)h * 1024 + np]);
}
__global__ __launch_bounds__(256)
void cc_prep(const float* __restrict__ Cw) {
    int idx = blockIdx.x * 256 + threadIdx.x;   // 0 .. 524287
    int j  = idx & 511;
    int kp = idx >> 9;          // 0..1023
    int n  = kp >> 1, c = kp & 1;
    float v = Cw[(size_t)c * HD * ND + (size_t)n * ND + j];
    g_ct[(size_t)j * 1024 + kp] = tf32r(c ? -v : v);
}

// -------- GEMM1: D[l][n'] = u @ B'^T via mma.sync + ldmatrix + cp.async -----
__global__ __launch_bounds__(256)
void gemm_bu_mma(const int* __restrict__ lengths) {
    extern __shared__ float sm[];
    uint32_t sA = (uint32_t)__cvta_generic_to_shared(sm);
    uint32_t sB = sA + 2 * ABYTES;

    int tid = threadIdx.x, wid = tid >> 5, lane = tid & 31;
    int g = lane >> 2, t = lane & 3;
    int wm = wid >> 1, wn = wid & 1;
    int np0 = blockIdx.x * 128;
    int b   = blockIdx.y >> 5;
    int l0  = (blockIdx.y & 31) * 128;

    const float* ua = g_ut + ((size_t)b * LS + l0) * HD;
    const float* bb = g_bt + (size_t)np0 * 512;

    // ldmatrix per-lane bases
    int lr8 = lane & 7, lm = lane >> 3;
    int rsel = (lm & 1) * 8, csel = (lm >> 1) * 4;
    uint32_t aB[2], bBp[4];
#pragma unroll
    for (int mi = 0; mi < 2; mi++)
        aB[mi] = sA + ((wm * 32 + mi * 16 + rsel + lr8) * PAD + csel) * 4;
#pragma unroll
    for (int p = 0; p < 4; p++)
        bBp[p] = sB + ((wn * 64 + p * 16 + rsel + lr8) * PAD + csel) * 4;

    // cp.async per-thread tile coords
    int crow = tid >> 3, cc4 = tid & 7;

    float acc[2][8][4];
#pragma unroll
    for (int mi = 0; mi < 2; mi++)
#pragma unroll
        for (int ni = 0; ni < 8; ni++)
#pragma unroll
            for (int q = 0; q < 4; q++) acc[mi][ni][q] = 0.f;

#define G1_LOAD(c_, buf_)                                                      \
    {                                                                          \
        int k0_ = (c_) * 32;                                                   \
        uint32_t da_ = sA + (buf_) * ABYTES, db_ = sB + (buf_) * ABYTES;       \
        _Pragma("unroll")                                                      \
        for (int i_ = 0; i_ < 4; i_++) {                                       \
            int r_ = crow + 32 * i_;                                           \
            cpa16(da_ + (r_ * PAD + cc4 * 4) * 4,                              \
                  ua + (size_t)r_ * HD + k0_ + cc4 * 4);                       \
            cpa16(db_ + (r_ * PAD + cc4 * 4) * 4,                              \
                  bb + (size_t)r_ * 512 + k0_ + cc4 * 4);                      \
        }                                                                      \
        CP_COMMIT();                                                           \
    }

    G1_LOAD(0, 0);
    for (int c = 0; c < 16; c++) {
        int buf = c & 1;
        if (c < 15) { G1_LOAD(c + 1, buf ^ 1); CP_WAIT(1); }
        else        { CP_WAIT(0); }
        __syncthreads();
        uint32_t boff = buf * ABYTES;
#pragma unroll
        for (int ks = 0; ks < 4; ks++) {
            int kb4 = ks * 32;
            uint32_t a0[4], a1[4];
            ldsm4(a0, aB[0] + boff + kb4);
            ldsm4(a1, aB[1] + boff + kb4);
#pragma unroll
            for (int p = 0; p < 4; p++) {
                uint32_t bf[4];
                ldsm4(bf, bBp[p] + boff + kb4);
                mma8(acc[0][2 * p],     a0, bf[0], bf[2]);
                mma8(acc[1][2 * p],     a1, bf[0], bf[2]);
                mma8(acc[0][2 * p + 1], a0, bf[1], bf[3]);
                mma8(acc[1][2 * p + 1], a1, bf[1], bf[3]);
            }
        }
        __syncthreads();
    }

    int len = lengths[b];
#pragma unroll
    for (int mi = 0; mi < 2; mi++) {
        int l_lo = l0 + wm * 32 + mi * 16 + g;
        int l_hi = l_lo + 8;
        bool v0 = l_lo < len, v1 = l_hi < len;
#pragma unroll
        for (int ni = 0; ni < 8; ni++) {
            int n = (np0 >> 1) + wn * 32 + ni * 4 + t;
            float2* row = &g_bu[((size_t)(b * ND + n)) * LS];
            row[l_lo] = v0 ? make_float2(acc[mi][ni][0], acc[mi][ni][1])
                           : make_float2(0.f, 0.f);
            row[l_hi] = v1 ? make_float2(acc[mi][ni][2], acc[mi][ni][3])
                           : make_float2(0.f, 0.f);
        }
    }
}

// ---------------- Scan phase A ----------------------------------------------
__global__ __launch_bounds__(256)
void scanA(const float* __restrict__ nu_log, const float* __restrict__ th_log) {
    int gw   = (blockIdx.x * 256 + threadIdx.x) >> 5;
    int lane = threadIdx.x & 31;
    int chunk = gw & (NCH - 1);
    int n     = (gw >> 5) & (ND - 1);
    int b     = gw >> 14;

    float lr, li;
    lam_of(n, nu_log, th_log, lr, li);
    bool rev = (n >= NHALF);

    float2* base = g_bu + ((size_t)(b * ND + n)) * LS;
    int t0 = chunk * CHL + lane * 4;
    int pb = LS - 4 - t0;

    float cr[4], ci[4];
    if (!rev) {
        float4 f0 = *(const float4*)(base + t0);
        float4 f1 = *(const float4*)(base + t0 + 2);
        cr[0] = f0.x; ci[0] = f0.y; cr[1] = f0.z; ci[1] = f0.w;
        cr[2] = f1.x; ci[2] = f1.y; cr[3] = f1.z; ci[3] = f1.w;
    } else {
        float4 f0 = *(const float4*)(base + pb);
        float4 f1 = *(const float4*)(base + pb + 2);
        cr[0] = f1.z; ci[0] = f1.w; cr[1] = f1.x; ci[1] = f1.y;
        cr[2] = f0.z; ci[2] = f0.w; cr[3] = f0.x; ci[3] = f0.y;
    }

    float yr[4], yi[4];
    yr[0] = cr[0]; yi[0] = ci[0];
#pragma unroll
    for (int i = 1; i < 4; i++) {
        yr[i] = fmaf(lr, yr[i - 1], fmaf(-li, yi[i - 1], cr[i]));
        yi[i] = fmaf(lr, yi[i - 1], fmaf( li, yr[i - 1], ci[i]));
    }

    float l2r = lr * lr - li * li, l2i = 2.f * lr * li;
    float fr  = l2r * l2r - l2i * l2i, fi = 2.f * l2r * l2i;

    float sr = yr[3], si = yi[3];
#pragma unroll
    for (int s = 1; s < 32; s <<= 1) {
        float pr_ = __shfl_up_sync(0xffffffffu, sr, s);
        float pi_ = __shfl_up_sync(0xffffffffu, si, s);
        if (lane >= s) {
            sr = fmaf(fr, pr_, fmaf(-fi, pi_, sr));
            si = fmaf(fr, pi_, fmaf( fi, pr_, si));
        }
        float nfr = fr * fr - fi * fi;
        fi = 2.f * fr * fi;
        fr = nfr;
    }
    float car = __shfl_up_sync(0xffffffffu, sr, 1);
    float cai = __shfl_up_sync(0xffffffffu, si, 1);
    if (lane == 0) { car = 0.f; cai = 0.f; }

    float pr = lr, pi = li;
    float xr[4], xi[4];
#pragma unroll
    for (int i = 0; i < 4; i++) {
        xr[i] = yr[i] + pr * car - pi * cai;
        xi[i] = yi[i] + pr * cai + pi * car;
        float t = pr * lr - pi * li;
        pi = pr * li + pi * lr;
        pr = t;
    }

    if (lane == 31) g_carry[(b * NCH + chunk) * ND + n] = make_float2(sr, si);

    if (!rev) {
        *(float4*)(base + t0)     = make_float4(xr[0], xi[0], xr[1], xi[1]);
        *(float4*)(base + t0 + 2) = make_float4(xr[2], xi[2], xr[3], xi[3]);
    } else {
        *(float4*)(base + pb)     = make_float4(xr[3], xi[3], xr[2], xi[2]);
        *(float4*)(base + pb + 2) = make_float4(xr[1], xi[1], xr[0], xi[0]);
    }
}

// ---------------- Scan phase B: parallel warp scan over chunks ---------------
// One warp per (b, n): 4096 warps -> 512 blocks of 256.
__global__ __launch_bounds__(256)
void scanB(const float* __restrict__ nu_log, const float* __restrict__ th_log) {
    int t = blockIdx.x * 256 + threadIdx.x;
    int lane = t & 31;          // chunk index
    int w = t >> 5;             // (b, n)
    int n = w & (ND - 1), b = w >> 9;

    float lr, li;
    lam_of(n, nu_log, th_log, lr, li);
    float fr = lr, fi = li;     // -> lam^128 via 7 squarings
#pragma unroll
    for (int s = 0; s < 7; s++) {
        float t2 = fr * fr - fi * fi;
        fi = 2.f * fr * fi;
        fr = t2;
    }

    float2 s2 = g_carry[(b * NCH + lane) * ND + n];
    float sr = s2.x, si = s2.y;
#pragma unroll
    for (int s = 1; s < 32; s <<= 1) {
        float pr_ = __shfl_up_sync(0xffffffffu, sr, s);
        float pi_ = __shfl_up_sync(0xffffffffu, si, s);
        if (lane >= s) {
            sr = fmaf(fr, pr_, fmaf(-fi, pi_, sr));
            si = fmaf(fr, pi_, fmaf( fi, pr_, si));
        }
        float nfr = fr * fr - fi * fi;
        fi = 2.f * fr * fi;
        fr = nfr;
    }
    float er = __shfl_up_sync(0xffffffffu, sr, 1);
    float ei = __shfl_up_sync(0xffffffffu, si, 1);
    if (lane == 0) { er = 0.f; ei = 0.f; }
    g_cin[(b * NCH + lane) * ND + n] = make_float2(er, ei);
}

// ---------------- Scan phase C (writes tf32-rounded x) -----------------------
__global__ __launch_bounds__(256)
void scanC(const int* __restrict__ lengths, const float* __restrict__ nu_log,
           const float* __restrict__ th_log) {
    int gw   = (blockIdx.x * 256 + threadIdx.x) >> 5;
    int lane = threadIdx.x & 31;
    int chunk = gw & (NCH - 1);
    int n     = (gw >> 5) & (ND - 1);
    int b     = gw >> 14;

    float lr, li;
    lam_of(n, nu_log, th_log, lr, li);
    bool rev = (n >= NHALF);
    int len = lengths[b];

    float2* base = g_bu + ((size_t)(b * ND + n)) * LS;
    int t0 = chunk * CHL + lane * 4;
    int pb = LS - 4 - t0;

    float xr[4], xi[4];
    if (!rev) {
        float4 f0 = *(const float4*)(base + t0);
        float4 f1 = *(const float4*)(base + t0 + 2);
        xr[0] = f0.x; xi[0] = f0.y; xr[1] = f0.z; xi[1] = f0.w;
        xr[2] = f1.x; xi[2] = f1.y; xr[3] = f1.z; xi[3] = f1.w;
    } else {
        float4 f0 = *(const float4*)(base + pb);
        float4 f1 = *(const float4*)(base + pb + 2);
        xr[0] = f1.z; xi[0] = f1.w; xr[1] = f1.x; xi[1] = f1.y;
        xr[2] = f0.z; xi[2] = f0.w; xr[3] = f0.x; xi[3] = f0.y;
    }

    float2 C = g_cin[(b * NCH + chunk) * ND + n];

    float l2r = lr * lr - li * li, l2i = 2.f * lr * li;
    float f4r = l2r * l2r - l2i * l2i, f4i = 2.f * l2r * l2i;
    float p4r = 1.f, p4i = 0.f, qr = f4r, qi = f4i;
#pragma unroll
    for (int bit = 0; bit < 5; bit++) {
        if (lane & (1 << bit)) {
            float t2 = p4r * qr - p4i * qi;
            p4i = p4r * qi + p4i * qr;
            p4r = t2;
        }
        float t3 = qr * qr - qi * qi;
        qi = 2.f * qr * qi;
        qr = t3;
    }
    float pwr = p4r * lr - p4i * li;
    float pwi = p4r * li + p4i * lr;

#pragma unroll
    for (int i = 0; i < 4; i++) {
        xr[i] += pwr * C.x - pwi * C.y;
        xi[i] += pwr * C.y + pwi * C.x;
        float t2 = pwr * lr - pwi * li;
        pwi = pwr * li + pwi * lr;
        pwr = t2;
        int l = rev ? (LS - 1 - (t0 + i)) : (t0 + i);
        if (l >= len) { xr[i] = 0.f; xi[i] = 0.f; }
        xr[i] = tf32r(xr[i]);
        xi[i] = tf32r(xi[i]);
    }

    if (!rev) {
        *(float4*)(base + t0)     = make_float4(xr[0], xi[0], xr[1], xi[1]);
        *(float4*)(base + t0 + 2) = make_float4(xr[2], xi[2], xr[3], xi[3]);
    } else {
        *(float4*)(base + pb)     = make_float4(xr[3], xi[3], xr[2], xi[2]);
        *(float4*)(base + pb + 2) = make_float4(xr[1], xi[1], xr[0], xi[0]);
    }
}

// -------- GEMM2: y = x2 @ Cc via mma.sync + ldmatrix, pipelined --------------
__global__ __launch_bounds__(256)
void gemm_y_mma(float* __restrict__ out) {
    extern __shared__ float sm[];
    uint32_t sA = (uint32_t)__cvta_generic_to_shared(sm);
    uint32_t sB = sA + 2 * ABYTES;
    float* As = sm;                          // [2][128][PAD] (l rows, k' cols)

    int tid = threadIdx.x, wid = tid >> 5, lane = tid & 31;
    int g = lane >> 2, t = lane & 3;
    int wm = wid >> 1, wn = wid & 1;
    int j0 = blockIdx.x * 128;
    int b  = blockIdx.y >> 5;
    int l0 = (blockIdx.y & 31) * 128;

    const float* cb = g_ct + (size_t)j0 * 1024;

    int lr8 = lane & 7, lm = lane >> 3;
    int rsel = (lm & 1) * 8, csel = (lm >> 1) * 4;
    uint32_t aB[2], bBp[4];
#pragma unroll
    for (int mi = 0; mi < 2; mi++)
        aB[mi] = sA + ((wm * 32 + mi * 16 + rsel + lr8) * PAD + csel) * 4;
#pragma unroll
    for (int p = 0; p < 4; p++)
        bBp[p] = sB + ((wn * 64 + p * 16 + rsel + lr8) * PAD + csel) * 4;

    int crow = tid >> 3, cc4 = tid & 7;   // B cp.async coords
    int ani = tid >> 7;                    // A manual coords: base n-sub
    int ali = tid & 127;

    float acc[2][8][4];
#pragma unroll
    for (int mi = 0; mi < 2; mi++)
#pragma unroll
        for (int ni = 0; ni < 8; ni++)
#pragma unroll
            for (int q = 0; q < 4; q++) acc[mi][ni][q] = 0.f;

    float2 pf[8];

#define G2_BLOAD(c_, buf_)                                                     \
    {                                                                          \
        int k0_ = (c_) * 32;                                                   \
        uint32_t db_ = sB + (buf_) * ABYTES;                                   \
        _Pragma("unroll")                                                      \
        for (int i_ = 0; i_ < 4; i_++) {                                       \
            int r_ = crow + 32 * i_;                                           \
            cpa16(db_ + (r_ * PAD + cc4 * 4) * 4,                              \
                  cb + (size_t)r_ * 1024 + k0_ + cc4 * 4);                     \
        }                                                                      \
        CP_COMMIT();                                                           \
    }
#define G2_ALDG(c_)                                                            \
    {                                                                          \
        int nb_ = (c_) * 16;                                                   \
        _Pragma("unroll")                                                      \
        for (int i_ = 0; i_ < 8; i_++)                                         \
            pf[i_] = g_bu[((size_t)(b * ND + nb_ + ani + 2 * i_)) * LS + l0 + ali]; \
    }
#define G2_ASTS(buf_)                                                          \
    {                                                                          \
        float* ab_ = As + (buf_) * (128 * PAD);                                \
        _Pragma("unroll")                                                      \
        for (int i_ = 0; i_ < 8; i_++)                                         \
            *(float2*)&ab_[ali * PAD + 2 * (ani + 2 * i_)] = pf[i_];           \
    }

    G2_BLOAD(0, 0);
    G2_ALDG(0);
    G2_ASTS(0);
    CP_WAIT(0);
    __syncthreads();

    for (int c = 0; c < 32; c++) {
        int buf = c & 1;
        if (c < 31) { G2_BLOAD(c + 1, buf ^ 1); G2_ALDG(c + 1); }
        uint32_t boff = buf * ABYTES;
#pragma unroll
        for (int ks = 0; ks < 4; ks++) {
            int kb4 = ks * 32;
            uint32_t a0[4], a1[4];
            ldsm4(a0, aB[0] + boff + kb4);
            ldsm4(a1, aB[1] + boff + kb4);
#pragma unroll
            for (int p = 0; p < 4; p++) {
                uint32_t bf[4];
                ldsm4(bf, bBp[p] + boff + kb4);
                mma8(acc[0][2 * p],     a0, bf[0], bf[2]);
                mma8(acc[1][2 * p],     a1, bf[0], bf[2]);
                mma8(acc[0][2 * p + 1], a0, bf[1], bf[3]);
                mma8(acc[1][2 * p + 1], a1, bf[1], bf[3]);
            }
        }
        if (c < 31) { G2_ASTS(buf ^ 1); CP_WAIT(0); }
        __syncthreads();
    }

#pragma unroll
    for (int mi = 0; mi < 2; mi++) {
        int l_lo = l0 + wm * 32 + mi * 16 + g;
        int l_hi = l_lo + 8;
#pragma unroll
        for (int ni = 0; ni < 8; ni++) {
            int j = j0 + wn * 64 + ni * 8 + 2 * t;
            *(float2*)&out[((size_t)b * LS + l_lo) * HD + j] =
                make_float2(acc[mi][ni][0], acc[mi][ni][1]);
            *(float2*)&out[((size_t)b * LS + l_hi) * HD + j] =
                make_float2(acc[mi][ni][2], acc[mi][ni][3]);
        }
    }
}

extern "C" void kernel_launch(void* const* d_in, const int* in_sizes, int n_in,
                              void* d_out, int out_size) {
    const float* u         = (const float*)d_in[0];
    const int*   lengths   = (const int*)d_in[1];
    const float* nu_log    = (const float*)d_in[2];
    const float* theta_log = (const float*)d_in[3];
    const float* Bw        = (const float*)d_in[4];
    const float* Cw        = (const float*)d_in[5];
    float* out = (float*)d_out;

    static int attr_set = 0;
    if (!attr_set) {
        cudaFuncSetAttribute(gemm_bu_mma, cudaFuncAttributeMaxDynamicSharedMemorySize, 4 * ABYTES);
        cudaFuncSetAttribute(gemm_y_mma,  cudaFuncAttributeMaxDynamicSharedMemorySize, 4 * ABYTES);
        attr_set = 1;
    }

    prep_u<<<4096, 256>>>(u);
    bt_prep<<<2048, 256>>>(Bw);
    cc_prep<<<2048, 256>>>(Cw);

    dim3 g1(1024 / 128, (BS * LS) / 128);   // (8, 256)
    gemm_bu_mma<<<g1, 256, 4 * ABYTES>>>(lengths);

    scanA<<<16384, 256>>>(nu_log, theta_log);
    scanB<<<512, 256>>>(nu_log, theta_log);   // FIX: one warp per (b,n) -> 4096 warps
    scanC<<<16384, 256>>>(lengths, nu_log, theta_log);

    dim3 g2(HD / 128, (BS * LS) / 128);     // (4, 256)
    gemm_y_mma<<<g2, 256, 4 * ABYTES>>>(out);
}